// round 1
// baseline (speedup 1.0000x reference)
#include <cuda_runtime.h>

#define T    4096
#define DIM  1024
#define HID  4096
#define E    8
#define KTOP 2

#define BM 128
#define BN 128
#define BKK 8
#define MT (T / BM)   // 32 max row-tiles per expert

// ---------------- scratch (static device memory; no allocations) -------------
__device__ int   g_counts[E];
__device__ int   g_fill[E];
__device__ int   g_offsets[E + 1];
__device__ int   g_topk_e[T * KTOP];
__device__ float g_topk_p[T * KTOP];
__device__ int   g_row_token[T * KTOP];
__device__ int   g_tok_row[T * KTOP];
__device__ float g_H[(size_t)T * KTOP * HID];     // 128 MB: relu(x@w1+b1) rows
__device__ float g_Hout[(size_t)T * KTOP * DIM];  // 32 MB: per-row h@w2

// ---------------- init ------------------------------------------------------
__global__ void init_kernel() {
    int i = threadIdx.x;
    if (i < E) { g_counts[i] = 0; g_fill[i] = 0; }
}

// ---------------- gating: one warp per token --------------------------------
__global__ void gating_kernel(const float* __restrict__ x,
                              const float* __restrict__ gw,
                              const float* __restrict__ gb) {
    int warp = (blockIdx.x * blockDim.x + threadIdx.x) >> 5;
    int lane = threadIdx.x & 31;
    if (warp >= T) return;
    const float* xr = x + (size_t)warp * DIM;

    float acc[E];
#pragma unroll
    for (int e = 0; e < E; e++) acc[e] = 0.f;

    for (int d = lane; d < DIM; d += 32) {
        float xv = xr[d];
        float4 g0 = *(const float4*)(gw + d * E);
        float4 g1 = *(const float4*)(gw + d * E + 4);
        acc[0] += xv * g0.x; acc[1] += xv * g0.y;
        acc[2] += xv * g0.z; acc[3] += xv * g0.w;
        acc[4] += xv * g1.x; acc[5] += xv * g1.y;
        acc[6] += xv * g1.z; acc[7] += xv * g1.w;
    }
#pragma unroll
    for (int e = 0; e < E; e++) {
#pragma unroll
        for (int off = 16; off > 0; off >>= 1)
            acc[e] += __shfl_down_sync(0xffffffffu, acc[e], off);
    }

    if (lane == 0) {
        float lg[E];
        float m = -1e30f;
#pragma unroll
        for (int e = 0; e < E; e++) { lg[e] = acc[e] + gb[e]; m = fmaxf(m, lg[e]); }
        float s = 0.f;
#pragma unroll
        for (int e = 0; e < E; e++) { lg[e] = expf(lg[e] - m); s += lg[e]; }
        // top-2 (ties -> lower index, matching jax.lax.top_k)
        int e1 = 0;
#pragma unroll
        for (int e = 1; e < E; e++) if (lg[e] > lg[e1]) e1 = e;
        int e2 = (e1 == 0) ? 1 : 0;
#pragma unroll
        for (int e = 0; e < E; e++) if (e != e1 && e != e2 && lg[e] > lg[e2]) e2 = e;
        float inv = 1.0f / s;
        g_topk_e[warp * 2 + 0] = e1;
        g_topk_e[warp * 2 + 1] = e2;
        g_topk_p[warp * 2 + 0] = lg[e1] * inv;
        g_topk_p[warp * 2 + 1] = lg[e2] * inv;
        atomicAdd(&g_counts[e1], 1);
        atomicAdd(&g_counts[e2], 1);
    }
}

// ---------------- tiny exclusive scan over E --------------------------------
__global__ void scan_kernel() {
    if (threadIdx.x == 0) {
        int acc = 0;
        g_offsets[0] = 0;
        for (int e = 0; e < E; e++) { acc += g_counts[e]; g_offsets[e + 1] = acc; }
    }
}

// ---------------- assign rows (order within expert is irrelevant) -----------
__global__ void assign_kernel() {
    int t = blockIdx.x * blockDim.x + threadIdx.x;
    if (t >= T) return;
#pragma unroll
    for (int k = 0; k < KTOP; k++) {
        int e = g_topk_e[t * 2 + k];
        int slot = atomicAdd(&g_fill[e], 1);
        int row = g_offsets[e] + slot;
        g_row_token[row] = t;
        g_tok_row[t * 2 + k] = row;
    }
}

// ---------------- grouped GEMM1: H = relu(gather(x) @ w1[e] + b1[e]) --------
__global__ void __launch_bounds__(256)
gemm1_kernel(const float* __restrict__ x,
             const float* __restrict__ w1,
             const float* __restrict__ b1) {
    int e  = blockIdx.y >> 5;   // / MT
    int mt = blockIdx.y & 31;
    int cnt = g_counts[e];
    int m0 = mt * BM;
    if (m0 >= cnt) return;
    int n0 = blockIdx.x * BN;
    int base = g_offsets[e];

    __shared__ float As[BKK][BM];
    __shared__ float Bs[BKK][BN];
    __shared__ int   toks[BM];

    int tid = threadIdx.x;
    if (tid < BM) {
        int m = m0 + tid;
        toks[tid] = g_row_token[base + ((m < cnt) ? m : 0)];
    }
    __syncthreads();

    int tx = tid & 15;   // n direction (16)
    int ty = tid >> 4;   // m direction (16)
    float acc[8][8];
#pragma unroll
    for (int i = 0; i < 8; i++)
#pragma unroll
        for (int j = 0; j < 8; j++) acc[i][j] = 0.f;

    const float* wB = w1 + (size_t)e * DIM * HID;

    int arow = tid >> 1;          // 128 rows, 2 threads/row
    int aseg = (tid & 1) * 4;
    int brow = tid >> 5;          // 8 k-rows, 32 threads/row
    int bcol = (tid & 31) * 4;

    for (int k0 = 0; k0 < DIM; k0 += BKK) {
        float4 av = *(const float4*)(x + (size_t)toks[arow] * DIM + k0 + aseg);
        As[aseg + 0][arow] = av.x;
        As[aseg + 1][arow] = av.y;
        As[aseg + 2][arow] = av.z;
        As[aseg + 3][arow] = av.w;
        float4 bv = *(const float4*)(wB + (size_t)(k0 + brow) * HID + n0 + bcol);
        *(float4*)&Bs[brow][bcol] = bv;
        __syncthreads();
#pragma unroll
        for (int k = 0; k < BKK; k++) {
            float4 a0 = *(const float4*)&As[k][ty * 8];
            float4 a1 = *(const float4*)&As[k][ty * 8 + 4];
            float4 b0 = *(const float4*)&Bs[k][tx * 8];
            float4 b1v = *(const float4*)&Bs[k][tx * 8 + 4];
            float ra[8] = {a0.x, a0.y, a0.z, a0.w, a1.x, a1.y, a1.z, a1.w};
            float rb[8] = {b0.x, b0.y, b0.z, b0.w, b1v.x, b1v.y, b1v.z, b1v.w};
#pragma unroll
            for (int i = 0; i < 8; i++)
#pragma unroll
                for (int j = 0; j < 8; j++) acc[i][j] += ra[i] * rb[j];
        }
        __syncthreads();
    }

#pragma unroll
    for (int i = 0; i < 8; i++) {
        int m = m0 + ty * 8 + i;
        if (m >= cnt) continue;
        size_t hbase = (size_t)(base + m) * HID + n0 + tx * 8;
#pragma unroll
        for (int j = 0; j < 8; j++) {
            float v = acc[i][j] + b1[e * HID + n0 + tx * 8 + j];
            g_H[hbase + j] = fmaxf(v, 0.f);
        }
    }
}

// ---------------- grouped GEMM2: Hout = H @ w2[e] ---------------------------
__global__ void __launch_bounds__(256)
gemm2_kernel(const float* __restrict__ w2) {
    int e  = blockIdx.y >> 5;
    int mt = blockIdx.y & 31;
    int cnt = g_counts[e];
    int m0 = mt * BM;
    if (m0 >= cnt) return;
    int n0 = blockIdx.x * BN;   // DIM/BN = 8 tiles
    int base = g_offsets[e];

    __shared__ float As[BKK][BM];
    __shared__ float Bs[BKK][BN];

    int tid = threadIdx.x;
    int tx = tid & 15;
    int ty = tid >> 4;
    float acc[8][8];
#pragma unroll
    for (int i = 0; i < 8; i++)
#pragma unroll
        for (int j = 0; j < 8; j++) acc[i][j] = 0.f;

    const float* wB = w2 + (size_t)e * HID * DIM;

    int arow = tid >> 1;
    int aseg = (tid & 1) * 4;
    int brow = tid >> 5;
    int bcol = (tid & 31) * 4;

    // clamp gathered row for tile remainder (reads stay in-bounds, stores guarded)
    int am = m0 + arow;
    size_t arowidx = (size_t)(base + ((am < cnt) ? am : (cnt - 1)));

    for (int k0 = 0; k0 < HID; k0 += BKK) {
        float4 av = *(const float4*)(g_H + arowidx * HID + k0 + aseg);
        As[aseg + 0][arow] = av.x;
        As[aseg + 1][arow] = av.y;
        As[aseg + 2][arow] = av.z;
        As[aseg + 3][arow] = av.w;
        float4 bv = *(const float4*)(wB + (size_t)(k0 + brow) * DIM + n0 + bcol);
        *(float4*)&Bs[brow][bcol] = bv;
        __syncthreads();
#pragma unroll
        for (int k = 0; k < BKK; k++) {
            float4 a0 = *(const float4*)&As[k][ty * 8];
            float4 a1 = *(const float4*)&As[k][ty * 8 + 4];
            float4 b0 = *(const float4*)&Bs[k][tx * 8];
            float4 b1v = *(const float4*)&Bs[k][tx * 8 + 4];
            float ra[8] = {a0.x, a0.y, a0.z, a0.w, a1.x, a1.y, a1.z, a1.w};
            float rb[8] = {b0.x, b0.y, b0.z, b0.w, b1v.x, b1v.y, b1v.z, b1v.w};
#pragma unroll
            for (int i = 0; i < 8; i++)
#pragma unroll
                for (int j = 0; j < 8; j++) acc[i][j] += ra[i] * rb[j];
        }
        __syncthreads();
    }

#pragma unroll
    for (int i = 0; i < 8; i++) {
        int m = m0 + ty * 8 + i;
        if (m >= cnt) continue;
        size_t obase = (size_t)(base + m) * DIM + n0 + tx * 8;
#pragma unroll
        for (int j = 0; j < 8; j++) g_Hout[obase + j] = acc[i][j];
    }
}

// ---------------- combine: out[t] = sum_k p_k * (Hout[row_k] + b2[e_k]) -----
__global__ void combine_kernel(const float* __restrict__ b2,
                               float* __restrict__ out) {
    int t = blockIdx.x;
    int e1 = g_topk_e[t * 2 + 0], e2 = g_topk_e[t * 2 + 1];
    float p1 = g_topk_p[t * 2 + 0], p2 = g_topk_p[t * 2 + 1];
    int r1 = g_tok_row[t * 2 + 0], r2 = g_tok_row[t * 2 + 1];
    const float* h1 = g_Hout + (size_t)r1 * DIM;
    const float* h2 = g_Hout + (size_t)r2 * DIM;
    const float* bb1 = b2 + (size_t)e1 * DIM;
    const float* bb2 = b2 + (size_t)e2 * DIM;
    for (int d = threadIdx.x; d < DIM; d += blockDim.x) {
        out[(size_t)t * DIM + d] = p1 * (h1[d] + bb1[d]) + p2 * (h2[d] + bb2[d]);
    }
}

// ---------------- launch ----------------------------------------------------
extern "C" void kernel_launch(void* const* d_in, const int* in_sizes, int n_in,
                              void* d_out, int out_size) {
    const float* x   = (const float*)d_in[0];
    const float* gw  = (const float*)d_in[1];
    const float* gb  = (const float*)d_in[2];
    const float* w1  = (const float*)d_in[3];
    const float* b1  = (const float*)d_in[4];
    const float* w2  = (const float*)d_in[5];
    const float* b2  = (const float*)d_in[6];
    float* out = (float*)d_out;

    init_kernel<<<1, 32>>>();
    gating_kernel<<<T / 8, 256>>>(x, gw, gb);     // 8 warps/block -> 4096 warps
    scan_kernel<<<1, 32>>>();
    assign_kernel<<<T / 256, 256>>>();
    gemm1_kernel<<<dim3(HID / BN, E * MT), 256>>>(x, w1, b1);
    gemm2_kernel<<<dim3(DIM / BN, E * MT), 256>>>(w2);
    combine_kernel<<<T, 256>>>(b2, out);
}

// round 2
// speedup vs baseline: 1.0019x; 1.0019x over previous
#include <cuda_runtime.h>

#define T    4096
#define DIM  1024
#define HID  4096
#define E    8
#define KTOP 2

#define BM 128
#define BN 128
#define BKK 8
#define MT (T / BM)   // 32 max row-tiles per expert

// ---------------- scratch (static device memory; no allocations) -------------
__device__ int   g_counts[E];
__device__ int   g_fill[E];
__device__ int   g_offsets[E + 1];
__device__ int   g_topk_e[T * KTOP];
__device__ float g_topk_p[T * KTOP];
__device__ int   g_row_token[T * KTOP];
__device__ int   g_tok_row[T * KTOP];
__device__ float g_H[(size_t)T * KTOP * HID];     // 128 MB: relu(x@w1+b1) rows
__device__ float g_Hout[(size_t)T * KTOP * DIM];  // 32 MB: per-row h@w2

// ---------------- init ------------------------------------------------------
__global__ void init_kernel() {
    int i = threadIdx.x;
    if (i < E) { g_counts[i] = 0; g_fill[i] = 0; }
}

// ---------------- gating: one warp per token --------------------------------
__global__ void gating_kernel(const float* __restrict__ x,
                              const float* __restrict__ gw,
                              const float* __restrict__ gb) {
    int warp = (blockIdx.x * blockDim.x + threadIdx.x) >> 5;
    int lane = threadIdx.x & 31;
    if (warp >= T) return;
    const float* xr = x + (size_t)warp * DIM;

    float acc[E];
#pragma unroll
    for (int e = 0; e < E; e++) acc[e] = 0.f;

    for (int d = lane; d < DIM; d += 32) {
        float xv = xr[d];
        float4 g0 = *(const float4*)(gw + d * E);
        float4 g1 = *(const float4*)(gw + d * E + 4);
        acc[0] += xv * g0.x; acc[1] += xv * g0.y;
        acc[2] += xv * g0.z; acc[3] += xv * g0.w;
        acc[4] += xv * g1.x; acc[5] += xv * g1.y;
        acc[6] += xv * g1.z; acc[7] += xv * g1.w;
    }
#pragma unroll
    for (int e = 0; e < E; e++) {
#pragma unroll
        for (int off = 16; off > 0; off >>= 1)
            acc[e] += __shfl_down_sync(0xffffffffu, acc[e], off);
    }

    if (lane == 0) {
        float lg[E];
        float m = -1e30f;
#pragma unroll
        for (int e = 0; e < E; e++) { lg[e] = acc[e] + gb[e]; m = fmaxf(m, lg[e]); }
        float s = 0.f;
#pragma unroll
        for (int e = 0; e < E; e++) { lg[e] = expf(lg[e] - m); s += lg[e]; }
        // top-2 (ties -> lower index, matching jax.lax.top_k)
        int e1 = 0;
#pragma unroll
        for (int e = 1; e < E; e++) if (lg[e] > lg[e1]) e1 = e;
        int e2 = (e1 == 0) ? 1 : 0;
#pragma unroll
        for (int e = 0; e < E; e++) if (e != e1 && e != e2 && lg[e] > lg[e2]) e2 = e;
        float inv = 1.0f / s;
        g_topk_e[warp * 2 + 0] = e1;
        g_topk_e[warp * 2 + 1] = e2;
        g_topk_p[warp * 2 + 0] = lg[e1] * inv;
        g_topk_p[warp * 2 + 1] = lg[e2] * inv;
        atomicAdd(&g_counts[e1], 1);
        atomicAdd(&g_counts[e2], 1);
    }
}

// ---------------- tiny exclusive scan over E --------------------------------
__global__ void scan_kernel() {
    if (threadIdx.x == 0) {
        int acc = 0;
        g_offsets[0] = 0;
        for (int e = 0; e < E; e++) { acc += g_counts[e]; g_offsets[e + 1] = acc; }
    }
}

// ---------------- assign rows (order within expert is irrelevant) -----------
__global__ void assign_kernel() {
    int t = blockIdx.x * blockDim.x + threadIdx.x;
    if (t >= T) return;
#pragma unroll
    for (int k = 0; k < KTOP; k++) {
        int e = g_topk_e[t * 2 + k];
        int slot = atomicAdd(&g_fill[e], 1);
        int row = g_offsets[e] + slot;
        g_row_token[row] = t;
        g_tok_row[t * 2 + k] = row;
    }
}

// ---------------- grouped GEMM1: H = relu(gather(x) @ w1[e] + b1[e]) --------
__global__ void __launch_bounds__(256)
gemm1_kernel(const float* __restrict__ x,
             const float* __restrict__ w1,
             const float* __restrict__ b1) {
    int e  = blockIdx.y >> 5;   // / MT
    int mt = blockIdx.y & 31;
    int cnt = g_counts[e];
    int m0 = mt * BM;
    if (m0 >= cnt) return;
    int n0 = blockIdx.x * BN;
    int base = g_offsets[e];

    __shared__ float As[BKK][BM];
    __shared__ float Bs[BKK][BN];
    __shared__ int   toks[BM];

    int tid = threadIdx.x;
    if (tid < BM) {
        int m = m0 + tid;
        toks[tid] = g_row_token[base + ((m < cnt) ? m : 0)];
    }
    __syncthreads();

    int tx = tid & 15;   // n direction (16)
    int ty = tid >> 4;   // m direction (16)
    float acc[8][8];
#pragma unroll
    for (int i = 0; i < 8; i++)
#pragma unroll
        for (int j = 0; j < 8; j++) acc[i][j] = 0.f;

    const float* wB = w1 + (size_t)e * DIM * HID;

    int arow = tid >> 1;          // 128 rows, 2 threads/row
    int aseg = (tid & 1) * 4;
    int brow = tid >> 5;          // 8 k-rows, 32 threads/row
    int bcol = (tid & 31) * 4;

    for (int k0 = 0; k0 < DIM; k0 += BKK) {
        float4 av = *(const float4*)(x + (size_t)toks[arow] * DIM + k0 + aseg);
        As[aseg + 0][arow] = av.x;
        As[aseg + 1][arow] = av.y;
        As[aseg + 2][arow] = av.z;
        As[aseg + 3][arow] = av.w;
        float4 bv = *(const float4*)(wB + (size_t)(k0 + brow) * HID + n0 + bcol);
        *(float4*)&Bs[brow][bcol] = bv;
        __syncthreads();
#pragma unroll
        for (int k = 0; k < BKK; k++) {
            float4 a0 = *(const float4*)&As[k][ty * 8];
            float4 a1 = *(const float4*)&As[k][ty * 8 + 4];
            float4 b0 = *(const float4*)&Bs[k][tx * 8];
            float4 b1v = *(const float4*)&Bs[k][tx * 8 + 4];
            float ra[8] = {a0.x, a0.y, a0.z, a0.w, a1.x, a1.y, a1.z, a1.w};
            float rb[8] = {b0.x, b0.y, b0.z, b0.w, b1v.x, b1v.y, b1v.z, b1v.w};
#pragma unroll
            for (int i = 0; i < 8; i++)
#pragma unroll
                for (int j = 0; j < 8; j++) acc[i][j] += ra[i] * rb[j];
        }
        __syncthreads();
    }

#pragma unroll
    for (int i = 0; i < 8; i++) {
        int m = m0 + ty * 8 + i;
        if (m >= cnt) continue;
        size_t hbase = (size_t)(base + m) * HID + n0 + tx * 8;
#pragma unroll
        for (int j = 0; j < 8; j++) {
            float v = acc[i][j] + b1[e * HID + n0 + tx * 8 + j];
            g_H[hbase + j] = fmaxf(v, 0.f);
        }
    }
}

// ---------------- grouped GEMM2: Hout = H @ w2[e] ---------------------------
__global__ void __launch_bounds__(256)
gemm2_kernel(const float* __restrict__ w2) {
    int e  = blockIdx.y >> 5;
    int mt = blockIdx.y & 31;
    int cnt = g_counts[e];
    int m0 = mt * BM;
    if (m0 >= cnt) return;
    int n0 = blockIdx.x * BN;   // DIM/BN = 8 tiles
    int base = g_offsets[e];

    __shared__ float As[BKK][BM];
    __shared__ float Bs[BKK][BN];

    int tid = threadIdx.x;
    int tx = tid & 15;
    int ty = tid >> 4;
    float acc[8][8];
#pragma unroll
    for (int i = 0; i < 8; i++)
#pragma unroll
        for (int j = 0; j < 8; j++) acc[i][j] = 0.f;

    const float* wB = w2 + (size_t)e * HID * DIM;

    int arow = tid >> 1;
    int aseg = (tid & 1) * 4;
    int brow = tid >> 5;
    int bcol = (tid & 31) * 4;

    // clamp gathered row for tile remainder (reads stay in-bounds, stores guarded)
    int am = m0 + arow;
    size_t arowidx = (size_t)(base + ((am < cnt) ? am : (cnt - 1)));

    for (int k0 = 0; k0 < HID; k0 += BKK) {
        float4 av = *(const float4*)(g_H + arowidx * HID + k0 + aseg);
        As[aseg + 0][arow] = av.x;
        As[aseg + 1][arow] = av.y;
        As[aseg + 2][arow] = av.z;
        As[aseg + 3][arow] = av.w;
        float4 bv = *(const float4*)(wB + (size_t)(k0 + brow) * DIM + n0 + bcol);
        *(float4*)&Bs[brow][bcol] = bv;
        __syncthreads();
#pragma unroll
        for (int k = 0; k < BKK; k++) {
            float4 a0 = *(const float4*)&As[k][ty * 8];
            float4 a1 = *(const float4*)&As[k][ty * 8 + 4];
            float4 b0 = *(const float4*)&Bs[k][tx * 8];
            float4 b1v = *(const float4*)&Bs[k][tx * 8 + 4];
            float ra[8] = {a0.x, a0.y, a0.z, a0.w, a1.x, a1.y, a1.z, a1.w};
            float rb[8] = {b0.x, b0.y, b0.z, b0.w, b1v.x, b1v.y, b1v.z, b1v.w};
#pragma unroll
            for (int i = 0; i < 8; i++)
#pragma unroll
                for (int j = 0; j < 8; j++) acc[i][j] += ra[i] * rb[j];
        }
        __syncthreads();
    }

#pragma unroll
    for (int i = 0; i < 8; i++) {
        int m = m0 + ty * 8 + i;
        if (m >= cnt) continue;
        size_t obase = (size_t)(base + m) * DIM + n0 + tx * 8;
#pragma unroll
        for (int j = 0; j < 8; j++) g_Hout[obase + j] = acc[i][j];
    }
}

// ---------------- combine: out[t] = sum_k p_k * (Hout[row_k] + b2[e_k]) -----
__global__ void combine_kernel(const float* __restrict__ b2,
                               float* __restrict__ out) {
    int t = blockIdx.x;
    int e1 = g_topk_e[t * 2 + 0], e2 = g_topk_e[t * 2 + 1];
    float p1 = g_topk_p[t * 2 + 0], p2 = g_topk_p[t * 2 + 1];
    int r1 = g_tok_row[t * 2 + 0], r2 = g_tok_row[t * 2 + 1];
    const float* h1 = g_Hout + (size_t)r1 * DIM;
    const float* h2 = g_Hout + (size_t)r2 * DIM;
    const float* bb1 = b2 + (size_t)e1 * DIM;
    const float* bb2 = b2 + (size_t)e2 * DIM;
    for (int d = threadIdx.x; d < DIM; d += blockDim.x) {
        out[(size_t)t * DIM + d] = p1 * (h1[d] + bb1[d]) + p2 * (h2[d] + bb2[d]);
    }
}

// ---------------- launch ----------------------------------------------------
extern "C" void kernel_launch(void* const* d_in, const int* in_sizes, int n_in,
                              void* d_out, int out_size) {
    const float* x   = (const float*)d_in[0];
    const float* gw  = (const float*)d_in[1];
    const float* gb  = (const float*)d_in[2];
    const float* w1  = (const float*)d_in[3];
    const float* b1  = (const float*)d_in[4];
    const float* w2  = (const float*)d_in[5];
    const float* b2  = (const float*)d_in[6];
    float* out = (float*)d_out;

    init_kernel<<<1, 32>>>();
    gating_kernel<<<T / 8, 256>>>(x, gw, gb);     // 8 warps/block -> 4096 warps
    scan_kernel<<<1, 32>>>();
    assign_kernel<<<T / 256, 256>>>();
    gemm1_kernel<<<dim3(HID / BN, E * MT), 256>>>(x, w1, b1);
    gemm2_kernel<<<dim3(DIM / BN, E * MT), 256>>>(w2);
    combine_kernel<<<T, 256>>>(b2, out);
}